// round 17
// baseline (speedup 1.0000x reference)
#include <cuda_runtime.h>
#include <cuda_fp16.h>
#include <math.h>

// ---------------------------------------------------------------------------
// VQ-VAE forward. B=16, D=256, K=512.
// BIT-FROZEN: enc1/enc2/prevq convs (ascending kw-major ci-fastest FMA chain),
// VQ argmin, z_e / z_q outputs.
// DECODER (tolerance 1e-3): post & dec1 mma.sync fp16 NHWC; dec2 halo-smem.
// Output: [x_recon 3145728][z_e 16777216][z_q 16777216][perp 1]
// ---------------------------------------------------------------------------

#define OFF_ZE   3145728
#define OFF_ZQ   19922944
#define OFF_PERP 36700160

typedef unsigned long long u64;
typedef unsigned int u32t;

__device__ __forceinline__ void ffma2(u64& acc, u64 a, u64 b)
{
    asm("fma.rn.f32x2 %0, %1, %2, %0;" : "+l"(acc) : "l"(a), "l"(b));
}
__device__ __forceinline__ u64 dup2(float x)
{
    u64 r;
    asm("mov.b64 %0, {%1, %1};" : "=l"(r) : "r"(__float_as_uint(x)));
    return r;
}
__device__ __forceinline__ u64 pack2(float lo, float hi)
{
    u64 r;
    asm("mov.b64 %0, {%1, %2};" : "=l"(r)
        : "r"(__float_as_uint(lo)), "r"(__float_as_uint(hi)));
    return r;
}
__device__ __forceinline__ void unpack2(u64 v, float& lo, float& hi)
{
    unsigned a, b;
    asm("mov.b64 {%0, %1}, %2;" : "=r"(a), "=r"(b) : "l"(v));
    lo = __uint_as_float(a); hi = __uint_as_float(b);
}
__device__ __forceinline__ int pn(int n) { return n + ((n >> 5) << 2); }

__device__ __forceinline__ void mma16816(float* d, const u32t* a, const u32t* b)
{
    asm volatile(
        "mma.sync.aligned.m16n8k16.row.col.f32.f16.f16.f32 "
        "{%0,%1,%2,%3}, {%4,%5,%6,%7}, {%8,%9}, {%0,%1,%2,%3};"
        : "+f"(d[0]), "+f"(d[1]), "+f"(d[2]), "+f"(d[3])
        : "r"(a[0]), "r"(a[1]), "r"(a[2]), "r"(a[3]), "r"(b[0]), "r"(b[1]));
}

// ------------------------- scratch (device globals) -----------------------
__device__ float  g_h1[16 * 64 * 128 * 128];
__device__ float  g_h2[16 * 128 * 64 * 64];
__device__ __half g_zq_h[16 * 4096 * 256];     // dec_in NHWC fp16
__device__ __half g_d1h[16 * 16384 * 128];     // post out NHWC fp16
__device__ __half g_d2h[16 * 65536 * 64];      // dec1 out NHWC fp16
__device__ __half g_wt2_post[4 * 128 * 1024];  // [cls][co][tt*Cin+ci] fp16
__device__ __half g_wt2_dec1[4 * 64 * 512];
__device__ float  g_wc1[64 * 48];
__device__ float  g_wc2[128 * 1024];
__device__ float  g_wc3[256 * 1152];
__device__ float  g_esq[512];
__device__ int    g_counts[512];

template <int Cin, int Cout, int KS>
__global__ void repack_conv(const float* __restrict__ w, float* __restrict__ wr)
{
    int idx = blockIdx.x * 256 + threadIdx.x;
    if (idx >= Cout * Cin * KS * KS) return;
    int ci = idx % Cin;
    int t  = idx / Cin;
    int kh = t % KS;
    int t2 = t / KS;
    int kw = t2 % KS;
    int co = t2 / KS;
    wr[idx] = w[((co * Cin + ci) * KS + kh) * KS + kw];
}

// tconv weights -> fp16, k' = tt*Cin + ci per parity class
template <int Cin, int Cout>
__global__ void repack_t05(const float* __restrict__ w, __half* __restrict__ wt)
{
    int idx = blockIdx.x * 256 + threadIdx.x;
    if (idx >= 4 * Cout * Cin * 4) return;
    constexpr int K = Cin * 4;
    int kp  = idx % K;
    int co  = (idx / K) % Cout;
    int cls = idx / (K * Cout);
    int tt  = kp / Cin;
    int ci  = kp % Cin;
    int ph = cls >> 1, pw = cls & 1;
    int ty = tt >> 1,  tx = tt & 1;
    int kh = ph ? (ty ? 2 : 0) : (ty ? 3 : 1);
    int kw = pw ? (tx ? 2 : 0) : (tx ? 3 : 1);
    wt[idx] = __float2half_rn(w[((ci * Cout + co) * 4 + kh) * 4 + kw]);
}

// ---------- enc1: FFMA2 8x8 tile, BM=64(Cout) x BN=256 (bit-frozen) --------
__global__ void __launch_bounds__(256, 2)
conv_e1(const float* __restrict__ in, const float* __restrict__ w,
        const float* __restrict__ bias, float* __restrict__ out)
{
    constexpr int KK = 48;
    constexpr int NT = 3;

    __shared__ float As[2][16][64];
    __shared__ float Bs[2][16][288];

    const int t  = threadIdx.x;
    const int n0 = blockIdx.x * 256;
    const int b  = blockIdx.z;
    const int tm = t >> 5;          // 0..7  (m = tm*8..)
    const int tn = t & 31;          // 0..31 (n = tn*8..)

    const int a_m = t & 63;
    const int a_k = (t >> 6) * 4;   // 0,4,8,12
    const int bn  = t;
    const int pb  = pn(bn);

    const int nglob = n0 + bn;
    const int ho_b  = nglob >> 7;
    const int wo_b  = nglob & 127;
    const float* inb  = in + (size_t)b * 3 * 65536;
    const float* wrow = w + (size_t)a_m * KK + a_k;

    u64 acc[4][8];
#pragma unroll
    for (int p = 0; p < 4; p++)
#pragma unroll
        for (int j = 0; j < 8; j++) acc[p][j] = 0ull;

    const int pnb = pn(tn * 8);

    float4 av;
    float  bv[16];

#define E1_LOAD(KB)                                                          \
    {                                                                        \
        av = *(const float4*)(wrow + (KB));                                  \
        _Pragma("unroll")                                                    \
        for (int i = 0; i < 16; i++) {                                       \
            int kk = (KB) + i;                                               \
            int ci = kk % 3;                                                 \
            int r  = kk / 3;                                                 \
            int kh = r & 3;                                                  \
            int kw = r >> 2;                                                 \
            int hi = ho_b * 2 - 1 + kh;                                      \
            int wi = wo_b * 2 - 1 + kw;                                      \
            float v = 0.f;                                                   \
            if (hi >= 0 && hi < 256 && wi >= 0 && wi < 256)                  \
                v = inb[(ci * 256 + hi) * 256 + wi];                         \
            bv[i] = v;                                                       \
        }                                                                    \
    }
#define E1_STORE(BUF)                                                        \
    {                                                                        \
        As[BUF][a_k + 0][a_m] = av.x; As[BUF][a_k + 1][a_m] = av.y;          \
        As[BUF][a_k + 2][a_m] = av.z; As[BUF][a_k + 3][a_m] = av.w;          \
        _Pragma("unroll")                                                    \
        for (int i = 0; i < 16; i++) Bs[BUF][i][pb] = bv[i];                 \
    }

    E1_LOAD(0);
    E1_STORE(0);
    __syncthreads();

    for (int it = 0; it < NT; it++) {
        const int cur = it & 1;
        if (it + 1 < NT) E1_LOAD((it + 1) * 16);

#pragma unroll
        for (int k = 0; k < 16; k++) {
            ulonglong2 ax = *(const ulonglong2*)&As[cur][k][tm * 8];
            ulonglong2 ay = *(const ulonglong2*)&As[cur][k][tm * 8 + 4];
            u64 A[4] = {ax.x, ax.y, ay.x, ay.y};
            float4 b0 = *(const float4*)&Bs[cur][k][pnb];
            float4 b1 = *(const float4*)&Bs[cur][k][pnb + 4];
            u64 bd[8] = {dup2(b0.x), dup2(b0.y), dup2(b0.z), dup2(b0.w),
                         dup2(b1.x), dup2(b1.y), dup2(b1.z), dup2(b1.w)};
#pragma unroll
            for (int p = 0; p < 4; p++)
#pragma unroll
                for (int j = 0; j < 8; j++) ffma2(acc[p][j], A[p], bd[j]);
        }
        if (it + 1 < NT) E1_STORE(cur ^ 1);
        __syncthreads();
    }
#undef E1_LOAD
#undef E1_STORE

#pragma unroll
    for (int p = 0; p < 4; p++) {
        int mlo = tm * 8 + 2 * p;
        float blo = bias[mlo], bhi = bias[mlo + 1];
#pragma unroll
        for (int j = 0; j < 8; j++) {
            float lo, hi;
            unpack2(acc[p][j], lo, hi);
            float v0 = fmaxf(lo + blo, 0.f);
            float v1 = fmaxf(hi + bhi, 0.f);
            int n = n0 + tn * 8 + j;
            out[((size_t)b * 64 + mlo) * 16384 + n]     = v0;
            out[((size_t)b * 64 + mlo + 1) * 16384 + n] = v1;
        }
    }
}

// ------- 8x8 f32x2 conv, double-buffered (enc2, prevq): bit-frozen ---------
template <int Cin, int Cout, int KS, int S, int P,
          int Hin, int Win, int Hout, int Wout, bool RELU, bool NHWC_OUT>
__global__ void __launch_bounds__(256, 2)
conv_gemm2(const float* __restrict__ in, const float* __restrict__ w,
           const float* __restrict__ bias, float* __restrict__ out)
{
    constexpr int KK   = Cin * KS * KS;
    constexpr int Npix = Hout * Wout;
    constexpr int NT   = KK / 16;

    __shared__ float As[2][16][128];
    __shared__ float Bs[2][16][144];

    const int t  = threadIdx.x;
    const int n0 = blockIdx.x * 128;
    const int m0 = blockIdx.y * 128;
    const int b  = blockIdx.z;
    const int tm = t >> 4;
    const int tn = t & 15;

    const int a_m = t >> 1;
    const int a_k = (t & 1) * 8;
    const int bn  = t & 127;
    const int kk0 = (t >> 7) * 8;
    const int pb  = pn(bn);

    const int nglob = n0 + bn;
    const int ho_b  = nglob / Wout;
    const int wo_b  = nglob - ho_b * Wout;
    const float* inb = in + (size_t)b * Cin * Hin * Win;
    const float* wrow = w + (size_t)(m0 + a_m) * KK + a_k;

    u64 acc[4][8];
#pragma unroll
    for (int p = 0; p < 4; p++)
#pragma unroll
        for (int j = 0; j < 8; j++) acc[p][j] = 0ull;

    const int pnb = pn(tn * 8);

    float4 av0, av1;
    float  bv[8];

#define LOAD_TILE(KB)                                                        \
    {                                                                        \
        av0 = *(const float4*)(wrow + (KB));                                 \
        av1 = *(const float4*)(wrow + (KB) + 4);                             \
        _Pragma("unroll")                                                    \
        for (int i = 0; i < 8; i++) {                                        \
            int kk = (KB) + kk0 + i;                                         \
            int ci = kk % Cin;                                               \
            int r  = kk / Cin;                                               \
            int kh = r % KS;                                                 \
            int kw = r / KS;                                                 \
            int hi = ho_b * S - P + kh;                                      \
            int wi = wo_b * S - P + kw;                                      \
            float v = 0.f;                                                   \
            if (hi >= 0 && hi < Hin && wi >= 0 && wi < Win)                  \
                v = inb[(ci * Hin + hi) * Win + wi];                         \
            bv[i] = v;                                                       \
        }                                                                    \
    }
#define STORE_TILE(BUF)                                                      \
    {                                                                        \
        As[BUF][a_k + 0][a_m] = av0.x; As[BUF][a_k + 1][a_m] = av0.y;        \
        As[BUF][a_k + 2][a_m] = av0.z; As[BUF][a_k + 3][a_m] = av0.w;        \
        As[BUF][a_k + 4][a_m] = av1.x; As[BUF][a_k + 5][a_m] = av1.y;        \
        As[BUF][a_k + 6][a_m] = av1.z; As[BUF][a_k + 7][a_m] = av1.w;        \
        _Pragma("unroll")                                                    \
        for (int i = 0; i < 8; i++) Bs[BUF][kk0 + i][pb] = bv[i];            \
    }

    LOAD_TILE(0);
    STORE_TILE(0);
    __syncthreads();

    for (int it = 0; it < NT; it++) {
        const int cur = it & 1;
        if (it + 1 < NT) LOAD_TILE((it + 1) * 16);

#pragma unroll
        for (int k = 0; k < 16; k++) {
            ulonglong2 ax = *(const ulonglong2*)&As[cur][k][tm * 8];
            ulonglong2 ay = *(const ulonglong2*)&As[cur][k][tm * 8 + 4];
            u64 A[4] = {ax.x, ax.y, ay.x, ay.y};
            float4 b0 = *(const float4*)&Bs[cur][k][pnb];
            float4 b1 = *(const float4*)&Bs[cur][k][pnb + 4];
            u64 bd[8] = {dup2(b0.x), dup2(b0.y), dup2(b0.z), dup2(b0.w),
                         dup2(b1.x), dup2(b1.y), dup2(b1.z), dup2(b1.w)};
#pragma unroll
            for (int p = 0; p < 4; p++)
#pragma unroll
                for (int j = 0; j < 8; j++) ffma2(acc[p][j], A[p], bd[j]);
        }
        if (it + 1 < NT) STORE_TILE(cur ^ 1);
        __syncthreads();
    }
#undef LOAD_TILE
#undef STORE_TILE

#pragma unroll
    for (int p = 0; p < 4; p++) {
        int mlo = m0 + tm * 8 + 2 * p;
        float blo = bias[mlo], bhi = bias[mlo + 1];
#pragma unroll
        for (int j = 0; j < 8; j++) {
            float lo, hi;
            unpack2(acc[p][j], lo, hi);
            float v0 = lo + blo;
            float v1 = hi + bhi;
            if (RELU) { v0 = fmaxf(v0, 0.f); v1 = fmaxf(v1, 0.f); }
            int n = n0 + tn * 8 + j;
            if (NHWC_OUT) {
                out[((size_t)b * Npix + n) * Cout + mlo]     = v0;
                out[((size_t)b * Npix + n) * Cout + mlo + 1] = v1;
            } else {
                out[((size_t)b * Cout + mlo) * Npix + n]       = v0;
                out[((size_t)b * Cout + mlo + 1) * Npix + n]   = v1;
            }
        }
    }
}

// --------- mma.sync fp16 convT (post, dec1), NHWC, tt-major k --------------
template <int Cin, int Cout, int Hin, int Win, bool RELU, int BPIX>
__global__ void __launch_bounds__(256)
tconv_mma(const __half* __restrict__ in, const __half* __restrict__ wt,
          const float* __restrict__ bias, __half* __restrict__ outh)
{
    constexpr int K     = Cin * 4;
    constexpr int NT    = K / 16;
    constexpr int Hout  = Hin * 2;
    constexpr int Wout  = Win * 2;
    constexpr int NpixI = Hin * Win;
    constexpr int NpixO = Hout * Wout;
    constexpr int WPIX  = BPIX / 32;
    constexpr int APU   = BPIX * 2 / 256;

    __shared__ __half Ah[2][BPIX][24];
    __shared__ __half Bh[2][Cout][24];

    const int t   = threadIdx.x;
    const int wid = t >> 5;
    const int l   = t & 31;
    const int g   = l >> 2;
    const int tg  = l & 3;
    const int wpr = (wid % WPIX) * 32;
    const int wpc = (wid / WPIX) * 64;

    const int n0  = blockIdx.x * BPIX;
    const int cls = blockIdx.y;
    const int ph  = cls >> 1;
    const int pw  = cls & 1;
    const int b   = blockIdx.z;

    const __half* inb = in + (size_t)b * NpixI * Cin;
    const __half* wcl = wt + (size_t)cls * Cout * K;

    int aoy[APU], aox[APU], aseg[APU];
#pragma unroll
    for (int i = 0; i < APU; i++) {
        int u   = i * 256 + t;
        int row = u >> 1;
        aseg[i] = (u & 1) * 8;
        int pix = n0 + row;
        aoy[i]  = pix / Win;
        aox[i]  = pix - aoy[i] * Win;
    }
    float acc[2][8][4];
#pragma unroll
    for (int fm = 0; fm < 2; fm++)
#pragma unroll
        for (int fn = 0; fn < 8; fn++)
#pragma unroll
            for (int q = 0; q < 4; q++) acc[fm][fn][q] = 0.f;

    uint4 av[APU];
    uint4 bv2[2];
    int   nb_cnt;

#define M_LOAD(KB)                                                           \
    {                                                                        \
        const int tt  = (KB) / Cin;                                          \
        const int cib = (KB) - tt * Cin;                                     \
        const int ty = tt >> 1, tx = tt & 1;                                 \
        _Pragma("unroll")                                                    \
        for (int i = 0; i < APU; i++) {                                      \
            int hi = aoy[i] + ph - ty;                                       \
            int wi = aox[i] + pw - tx;                                       \
            uint4 v = make_uint4(0, 0, 0, 0);                                \
            if (hi >= 0 && hi < Hin && wi >= 0 && wi < Win)                  \
                v = *(const uint4*)(inb + ((size_t)(hi * Win + wi)) * Cin    \
                                    + cib + aseg[i]);                        \
            av[i] = v;                                                       \
        }                                                                    \
        nb_cnt = 0;                                                          \
        _Pragma("unroll")                                                    \
        for (int i = 0; i < 2; i++) {                                        \
            int u = i * 256 + t;                                             \
            if (u < Cout * 2) {                                              \
                int co = u >> 1;                                             \
                int sg = (u & 1) * 8;                                        \
                bv2[nb_cnt++] = *(const uint4*)(wcl + (size_t)co * K + (KB) + sg); \
            }                                                                \
        }                                                                    \
    }
#define M_STORE(BUF)                                                         \
    {                                                                        \
        _Pragma("unroll")                                                    \
        for (int i = 0; i < APU; i++) {                                      \
            int u = i * 256 + t;                                             \
            *(uint4*)&Ah[BUF][u >> 1][(u & 1) * 8] = av[i];                  \
        }                                                                    \
        int c = 0;                                                           \
        _Pragma("unroll")                                                    \
        for (int i = 0; i < 2; i++) {                                        \
            int u = i * 256 + t;                                             \
            if (u < Cout * 2)                                                \
                *(uint4*)&Bh[BUF][u >> 1][(u & 1) * 8] = bv2[c++];           \
        }                                                                    \
    }

    M_LOAD(0);
    M_STORE(0);
    __syncthreads();

    for (int it = 0; it < NT; it++) {
        const int cur = it & 1;
        if (it + 1 < NT) M_LOAD((it + 1) * 16);

        u32t afr[2][4];
#pragma unroll
        for (int fm = 0; fm < 2; fm++) {
            int r = wpr + fm * 16 + g;
            afr[fm][0] = *(const u32t*)&Ah[cur][r][2 * tg];
            afr[fm][1] = *(const u32t*)&Ah[cur][r + 8][2 * tg];
            afr[fm][2] = *(const u32t*)&Ah[cur][r][2 * tg + 8];
            afr[fm][3] = *(const u32t*)&Ah[cur][r + 8][2 * tg + 8];
        }
#pragma unroll
        for (int fn = 0; fn < 8; fn++) {
            int co = wpc + fn * 8 + g;
            u32t bfr[2];
            bfr[0] = *(const u32t*)&Bh[cur][co][2 * tg];
            bfr[1] = *(const u32t*)&Bh[cur][co][2 * tg + 8];
#pragma unroll
            for (int fm = 0; fm < 2; fm++)
                mma16816(acc[fm][fn], afr[fm], bfr);
        }

        if (it + 1 < NT) M_STORE(cur ^ 1);
        __syncthreads();
    }
#undef M_LOAD
#undef M_STORE

#pragma unroll
    for (int fm = 0; fm < 2; fm++) {
#pragma unroll
        for (int e = 0; e < 2; e++) {
            int pix = n0 + wpr + fm * 16 + g + e * 8;
            int oy  = pix / Win;
            int ox  = pix - oy * Win;
            int po  = (2 * oy + ph) * Wout + (2 * ox + pw);
            __half* dst = outh + ((size_t)b * NpixO + po) * Cout;
#pragma unroll
            for (int fn = 0; fn < 8; fn++) {
                int co = wpc + fn * 8 + 2 * tg;
                float v0 = acc[fm][fn][2 * e]     + bias[co];
                float v1 = acc[fm][fn][2 * e + 1] + bias[co + 1];
                if (RELU) { v0 = fmaxf(v0, 0.f); v1 = fmaxf(v1, 0.f); }
                __half2 h;
                h.x = __float2half_rn(v0);
                h.y = __float2half_rn(v1);
                *(__half2*)(dst + co) = h;
            }
        }
    }
}

// ---------------- dec2: 3x3 conv from NHWC fp16, FFMA2 pairs ---------------
__global__ void __launch_bounds__(256)
dec2_kernel(const __half* __restrict__ in, const float* __restrict__ w,
            const float* __restrict__ bias, float* __restrict__ out)
{
    __shared__ __half Hs[324 * 66];        // 18x18 halo, pitch 66 halfs
    __shared__ float  wp01[9 * 128];       // [q][ci*2 + {co0,co1}]
    __shared__ float  wp2[9 * 64];         // [q][ci] co=2

    const int t  = threadIdx.x;
    const int b  = blockIdx.y;
    const int ty0 = (blockIdx.x >> 4) * 16;
    const int tx0 = (blockIdx.x & 15) * 16;

    for (int i = t; i < 9 * 128; i += 256) {
        int q  = i >> 7;
        int r  = i & 127;
        int ci = r >> 1;
        int co = r & 1;
        int kh = q / 3, kw = q % 3;
        wp01[i] = w[((ci * 3 + co) * 3 + (2 - kh)) * 3 + (2 - kw)];
    }
    for (int i = t; i < 9 * 64; i += 256) {
        int q  = i >> 6;
        int ci = i & 63;
        int kh = q / 3, kw = q % 3;
        wp2[i] = w[((ci * 3 + 2) * 3 + (2 - kh)) * 3 + (2 - kw)];
    }

    const __half* inb = in + (size_t)b * 65536 * 64;
    for (int u = t; u < 324 * 8; u += 256) {
        int row = u >> 3;
        int sg  = u & 7;
        int hy  = ty0 - 1 + row / 18;
        int hx  = tx0 - 1 + row % 18;
        uint4 v = make_uint4(0, 0, 0, 0);
        if (hy >= 0 && hy < 256 && hx >= 0 && hx < 256)
            v = *(const uint4*)(inb + ((size_t)(hy * 256 + hx)) * 64 + sg * 8);
        u32t* d = (u32t*)(Hs + row * 66 + sg * 8);
        d[0] = v.x; d[1] = v.y; d[2] = v.z; d[3] = v.w;
    }
    __syncthreads();

    const int ly = t >> 4;
    const int lx = t & 15;
    u64   acc01 = pack2(bias[0], bias[1]);
    float a2    = bias[2];
#pragma unroll
    for (int qy = 0; qy < 3; qy++)
#pragma unroll
        for (int qx = 0; qx < 3; qx++) {
            int q = qy * 3 + qx;
            const __half* hrow = Hs + ((ly + qy) * 18 + lx + qx) * 66;
            const float* p01 = wp01 + q * 128;
            const float* p2  = wp2  + q * 64;
            for (int c2 = 0; c2 < 32; c2++) {
                float2 f = __half22float2(*(const __half2*)(hrow + c2 * 2));
                ffma2(acc01, dup2(f.x), *(const u64*)(p01 + 4 * c2));
                a2 = __fmaf_rn(f.x, p2[2 * c2], a2);
                ffma2(acc01, dup2(f.y), *(const u64*)(p01 + 4 * c2 + 2));
                a2 = __fmaf_rn(f.y, p2[2 * c2 + 1], a2);
            }
        }
    float a0, a1;
    unpack2(acc01, a0, a1);
    int oy = ty0 + ly, ox = tx0 + lx;
    int p = oy * 256 + ox;
    out[((size_t)b * 3 + 0) * 65536 + p] = a0;
    out[((size_t)b * 3 + 1) * 65536 + p] = a1;
    out[((size_t)b * 3 + 2) * 65536 + p] = a2;
}

// ------------------------------- VQ (bit-frozen) ---------------------------
__global__ void zero_counts_kernel() { g_counts[threadIdx.x] = 0; }

__global__ void esq_kernel(const float* __restrict__ emb)
{
    int k = blockIdx.x * 128 + threadIdx.x;
    if (k < 512) {
        const float4* e = (const float4*)(emb + (size_t)k * 256);
        float s = 0.f;
#pragma unroll
        for (int i = 0; i < 64; i++) {
            float4 v = e[i];
            s += v.x * v.x + v.y * v.y + v.z * v.z + v.w * v.w;
        }
        g_esq[k] = s;
    }
}

__global__ void __launch_bounds__(256)
vq_kernel(const float* __restrict__ ze, const float* __restrict__ emb,
          float* __restrict__ zq_nhwc, __half* __restrict__ dec_h)
{
    __shared__ u64   Zsd[256][32];
    __shared__ float Es[32][64];
    __shared__ float zpart[32][8];
    __shared__ float zsqs[32];
    __shared__ float rbest[32][16];
    __shared__ int   rk[32][16];
    __shared__ int   fidx[32];

    const int t  = threadIdx.x;
    const int n0 = blockIdx.x * 32;
    const int tm = t >> 4;
    const int tn = t & 15;
    const int r0 = tm * 2, r1 = tm * 2 + 1;

#pragma unroll
    for (int j = 0; j < 8; j++) {
        int idx = t + 256 * j;
        int m   = idx >> 6;
        int kq  = idx & 63;
        float4 v = *(const float4*)(ze + ((size_t)(n0 + m)) * 256 + kq * 4);
        Zsd[kq * 4 + 0][m] = dup2(v.x); Zsd[kq * 4 + 1][m] = dup2(v.y);
        Zsd[kq * 4 + 2][m] = dup2(v.z); Zsd[kq * 4 + 3][m] = dup2(v.w);
    }
    __syncthreads();

    {
        int row = t & 31;
        int seg = t >> 5;
        float s = 0.f;
#pragma unroll
        for (int i = 0; i < 32; i++) {
            float v = ((const float*)&Zsd[seg * 32 + i][row])[0];
            s += v * v;
        }
        zpart[row][seg] = s;
    }
    __syncthreads();
    if (t < 32) {
        float s = zpart[t][0];
#pragma unroll
        for (int q = 1; q < 8; q++) s += zpart[t][q];
        zsqs[t] = s;
    }
    __syncthreads();

    const float zr0 = zsqs[r0];
    const float zr1 = zsqs[r1];

    float best[2] = {1e30f, 1e30f};
    int   bk[2]   = {0, 0};

    for (int e0 = 0; e0 < 512; e0 += 64) {
        u64 accP[8][2][2];
#pragma unroll
        for (int l = 0; l < 8; l++)
#pragma unroll
            for (int i = 0; i < 2; i++)
#pragma unroll
                for (int cp = 0; cp < 2; cp++) accP[l][i][cp] = 0ull;

        for (int kb = 0; kb < 256; kb += 32) {
            __syncthreads();
#pragma unroll
            for (int j = 0; j < 2; j++) {
                int idx = t + 256 * j;
                int e   = idx >> 3;
                int k4  = (idx & 7) * 4;
                float4 v = *(const float4*)(emb + (size_t)(e0 + e) * 256 + kb + k4);
                Es[k4 + 0][e] = v.x; Es[k4 + 1][e] = v.y;
                Es[k4 + 2][e] = v.z; Es[k4 + 3][e] = v.w;
            }
            __syncthreads();
#pragma unroll
            for (int k = 0; k < 32; k++) {
                const int l = k & 7;
                u64 A0 = Zsd[kb + k][r0];
                u64 A1 = Zsd[kb + k][r1];
                ulonglong2 B = *(const ulonglong2*)&Es[k][tn * 4];
                ffma2(accP[l][0][0], A0, B.x);
                ffma2(accP[l][0][1], A0, B.y);
                ffma2(accP[l][1][0], A1, B.x);
                ffma2(accP[l][1][1], A1, B.y);
            }
        }
#pragma unroll
        for (int i = 0; i < 2; i++) {
            float zr = (i == 0) ? zr0 : zr1;
#pragma unroll
            for (int cp = 0; cp < 2; cp++) {
                float v0[8], v1[8];
#pragma unroll
                for (int l = 0; l < 8; l++) unpack2(accP[l][i][cp], v0[l], v1[l]);
                {
                    float q0 = __fadd_rn(v0[0], v0[4]);
                    float q1 = __fadd_rn(v0[1], v0[5]);
                    float q2 = __fadd_rn(v0[2], v0[6]);
                    float q3 = __fadd_rn(v0[3], v0[7]);
                    float d  = __fadd_rn(__fadd_rn(q0, q2), __fadd_rn(q1, q3));
                    int kcode = e0 + tn * 4 + 2 * cp;
                    float eq = g_esq[kcode];
                    float s = __fadd_rn(__fadd_rn(zr, eq), -__fmul_rn(2.f, d));
                    if (s < best[i]) { best[i] = s; bk[i] = kcode; }
                }
                {
                    float q0 = __fadd_rn(v1[0], v1[4]);
                    float q1 = __fadd_rn(v1[1], v1[5]);
                    float q2 = __fadd_rn(v1[2], v1[6]);
                    float q3 = __fadd_rn(v1[3], v1[7]);
                    float d  = __fadd_rn(__fadd_rn(q0, q2), __fadd_rn(q1, q3));
                    int kcode = e0 + tn * 4 + 2 * cp + 1;
                    float eq = g_esq[kcode];
                    float s = __fadd_rn(__fadd_rn(zr, eq), -__fmul_rn(2.f, d));
                    if (s < best[i]) { best[i] = s; bk[i] = kcode; }
                }
            }
        }
    }
    __syncthreads();
    rbest[r0][tn] = best[0]; rk[r0][tn] = bk[0];
    rbest[r1][tn] = best[1]; rk[r1][tn] = bk[1];
    __syncthreads();
    if (t < 32) {
        float bs = rbest[t][0];
        int   bi = rk[t][0];
#pragma unroll
        for (int q = 1; q < 16; q++) {
            float s = rbest[t][q];
            int   k = rk[t][q];
            if (s < bs || (s == bs && k < bi)) { bs = s; bi = k; }
        }
        fidx[t] = bi;
        atomicAdd(&g_counts[bi], 1);
    }
    __syncthreads();

    // z_q NHWC fp32 (exact codebook rows)
#pragma unroll
    for (int j = 0; j < 8; j++) {
        int idx = t + 256 * j;
        int m   = idx >> 6;
        int d4  = idx & 63;
        float4 v = *(const float4*)(emb + (size_t)fidx[m] * 256 + d4 * 4);
        *(float4*)(zq_nhwc + ((size_t)(n0 + m)) * 256 + d4 * 4) = v;
    }
    // dec_in NHWC fp16: z_e + (z_q - z_e)
#pragma unroll
    for (int j = 0; j < 16; j++) {
        int u   = t + 256 * j;
        int m   = u >> 7;
        int d   = (u & 127) * 2;
        int n   = n0 + m;
        int code = fidx[m];
        float2 qv = *(const float2*)(emb + (size_t)code * 256 + d);
        float2 zv = *(const float2*)(ze + (size_t)n * 256 + d);
        float d0 = zv.x + (qv.x - zv.x);
        float d1 = zv.y + (qv.y - zv.y);
        __half2 h;
        h.x = __float2half_rn(d0);
        h.y = __float2half_rn(d1);
        *(__half2*)(dec_h + (size_t)n * 256 + d) = h;
    }
}

__global__ void perp_kernel(float* __restrict__ out)
{
    __shared__ float red[512];
    int t = threadIdx.x;
    float p = (float)g_counts[t] * (1.f / 65536.f);
    red[t] = p * logf(p + 1e-10f);
    __syncthreads();
    for (int s = 256; s > 0; s >>= 1) {
        if (t < s) red[t] += red[t + s];
        __syncthreads();
    }
    if (t == 0) out[0] = expf(-red[0]);
}

// ---------------------------------------------------------------------------
extern "C" void kernel_launch(void* const* d_in, const int* in_sizes, int n_in,
                              void* d_out, int out_size)
{
    const float* x      = (const float*)d_in[0];
    const float* w_enc1 = (const float*)d_in[1];
    const float* b_enc1 = (const float*)d_in[2];
    const float* w_enc2 = (const float*)d_in[3];
    const float* b_enc2 = (const float*)d_in[4];
    const float* w_prevq= (const float*)d_in[5];
    const float* b_prevq= (const float*)d_in[6];
    const float* emb    = (const float*)d_in[7];
    const float* w_post = (const float*)d_in[8];
    const float* b_post = (const float*)d_in[9];
    const float* w_dec1 = (const float*)d_in[10];
    const float* b_dec1 = (const float*)d_in[11];
    const float* w_dec2 = (const float*)d_in[12];
    const float* b_dec2 = (const float*)d_in[13];

    float* out  = (float*)d_out;
    float* ze   = out + OFF_ZE;
    float* zq   = out + OFF_ZQ;
    float* perp = out + OFF_PERP;

    void* p;
    cudaGetSymbolAddress(&p, g_h1);        float*  h1   = (float*)p;
    cudaGetSymbolAddress(&p, g_h2);        float*  h2   = (float*)p;
    cudaGetSymbolAddress(&p, g_zq_h);      __half* zqh  = (__half*)p;
    cudaGetSymbolAddress(&p, g_d1h);       __half* d1h  = (__half*)p;
    cudaGetSymbolAddress(&p, g_d2h);       __half* d2h  = (__half*)p;
    cudaGetSymbolAddress(&p, g_wt2_post);  __half* wtp  = (__half*)p;
    cudaGetSymbolAddress(&p, g_wt2_dec1);  __half* wtd  = (__half*)p;
    cudaGetSymbolAddress(&p, g_wc1);       float*  wc1  = (float*)p;
    cudaGetSymbolAddress(&p, g_wc2);       float*  wc2  = (float*)p;
    cudaGetSymbolAddress(&p, g_wc3);       float*  wc3  = (float*)p;

    zero_counts_kernel<<<1, 512>>>();
    esq_kernel<<<4, 128>>>(emb);
    repack_conv<3, 64, 4><<<12, 256>>>(w_enc1, wc1);
    repack_conv<64, 128, 4><<<512, 256>>>(w_enc2, wc2);
    repack_conv<128, 256, 3><<<1152, 256>>>(w_prevq, wc3);
    repack_t05<256, 128><<<2048, 256>>>(w_post, wtp);
    repack_t05<128, 64><<<512, 256>>>(w_dec1, wtd);

    // encoder (bit-frozen numerics; enc1 now FFMA2 8x8 — bit-identical)
    conv_e1<<<dim3(64, 1, 16), 256>>>(x, wc1, b_enc1, h1);
    conv_gemm2<64, 128, 4, 2, 1, 128, 128, 64, 64, true, false>
        <<<dim3(32, 1, 16), 256>>>(h1, wc2, b_enc2, h2);
    conv_gemm2<128, 256, 3, 1, 1, 64, 64, 64, 64, false, true>
        <<<dim3(32, 2, 16), 256>>>(h2, wc3, b_prevq, ze);

    vq_kernel<<<2048, 256>>>(ze, emb, zq, zqh);
    perp_kernel<<<1, 512>>>(perp);

    // decoder (mma.sync fp16, NHWC)
    tconv_mma<256, 128, 64, 64, false, 128>
        <<<dim3(32, 4, 16), 256>>>(zqh, wtp, b_post, d1h);
    tconv_mma<128, 64, 128, 128, true, 256>
        <<<dim3(64, 4, 16), 256>>>(d1h, wtd, b_dec1, d2h);
    dec2_kernel<<<dim3(256, 16), 256>>>(d2h, w_dec2, b_dec2, out);
}